// round 6
// baseline (speedup 1.0000x reference)
#include <cuda_runtime.h>
#include <cuda.h>
#include <cuda_fp16.h>
#include <cstdint>

#define B_DIM  4096
#define K_DIM  1024
#define NSOMA  16384
#define NNEUR  1024

#define NT     256
#define KC     64
#define PAIRS  74
#define NTILES 1024          // 16 m-pairs x 64 n-tiles
#define NSTAGE 5

#define STAGE_BYTES 32768    // A half (16KB) + B half (16KB) per CTA
#define TX_BYTES    65536    // 4 TMA loads (2 per CTA) per chunk into leader barrier

#define SM_TM       163840
#define SM_FULL(s)  (163856 + 8*(s))
#define SM_EMPTY(s) (163896 + 8*(s))
#define SM_MD(b)    (163936 + 8*(b))
#define SM_ED(b)    (163952 + 8*(b))
#define SM_BIAS(b)  (163968 + 2176*(b))
#define SMEM_BYTES  (163968 + 2*2176 + 1024)

// idesc kind::f16 cg2: D=F32(bit4), f16 A/B, N=256, M=256
#define MMA_IDESC ((1u << 4) | ((256 / 8) << 17) | ((256 / 16) << 24))

#if defined(__CUDA_ARCH_FEAT_SM103_ALL) || defined(__CUDA_ARCH_FEAT_SM100_ALL) || defined(__CUDA_ARCH_FEAT_SM101_ALL)
#define HAVE_TCGEN05 1
#else
#define HAVE_TCGEN05 0
#endif

__device__ __align__(1024) __half g_X16[(size_t)B_DIM * K_DIM];
__device__ __align__(1024) __half g_W16[(size_t)NSOMA * K_DIM];

static __device__ __forceinline__ uint32_t smem_u32(const void* p) {
    uint32_t a;
    asm("{ .reg .u64 t; cvta.to.shared.u64 t, %1; cvt.u32.u64 %0, t; }" : "=r"(a) : "l"(p));
    return a;
}

#define MBAR_INIT(a, c) \
    asm volatile("mbarrier.init.shared.b64 [%0], %1;" :: "r"((uint32_t)(a)), "r"((uint32_t)(c)) : "memory")
#define MBAR_EXPECT_TX(a, b) \
    asm volatile("mbarrier.arrive.expect_tx.shared.b64 _, [%0], %1;" :: "r"((uint32_t)(a)), "r"((uint32_t)(b)) : "memory")
#define MBAR_WAIT(a, p) do {                                                     \
    uint32_t _m = (uint32_t)(a), _p = (uint32_t)(p), _d;                         \
    asm volatile("{\n\t.reg .pred q;\n\t"                                        \
        "mbarrier.try_wait.parity.acquire.cta.shared::cta.b64 q, [%1], %2;\n\t"  \
        "selp.b32 %0, 1, 0, q;\n\t}" : "=r"(_d) : "r"(_m), "r"(_p) : "memory");  \
    if (!_d) {                                                                   \
        asm volatile("{\n\t.reg .pred Q;\n\t"                                    \
            "WL_%=:\n\t"                                                         \
            "mbarrier.try_wait.parity.acquire.cta.shared::cta.b64 Q, [%0], %1, 0x989680;\n\t" \
            "@Q bra.uni WD_%=;\n\tbra.uni WL_%=;\n\tWD_%=:\n\t}"                 \
            :: "r"(_m), "r"(_p) : "memory");                                     \
    }                                                                            \
} while (0)

#if HAVE_TCGEN05
#define TMA_2D_CG2(dst, tm, cx, cy, mbar) \
    asm volatile("{\n\t.reg .b32 lb;\n\t" \
                 "and.b32 lb, %4, 0xFEFFFFFF;\n\t" \
                 "cp.async.bulk.tensor.2d.cta_group::2.shared::cluster.global.tile.mbarrier::complete_tx::bytes " \
                 "[%0], [%1, {%2, %3}], [lb];\n\t}" \
                 :: "r"((uint32_t)(dst)), "l"(tm), "r"((int32_t)(cx)), "r"((int32_t)(cy)), \
                    "r"((uint32_t)(mbar)) : "memory")

#define TC_COMMIT_MC_CG2(mbar, mask) \
    asm volatile("tcgen05.commit.cta_group::2.mbarrier::arrive::one.shared::cluster.multicast::cluster.b64 [%0], %1;" \
                 :: "r"((uint32_t)(mbar)), "h"((uint16_t)(mask)) : "memory")

#define MBAR_ARRIVE_LEADER(a) \
    asm volatile("{\n\t.reg .b32 la;\n\tand.b32 la, %0, 0xFEFFFFFF;\n\t" \
                 "mbarrier.arrive.shared::cluster.b64 _, [la];\n\t}" \
                 :: "r"((uint32_t)(a)) : "memory")

#define CLUSTER_SYNC() do { \
    asm volatile("barrier.cluster.arrive.aligned;" ::: "memory"); \
    asm volatile("barrier.cluster.wait.aligned;" ::: "memory"); \
} while (0)

static __device__ __forceinline__ uint64_t make_desc(uint32_t addr) {
    const uint64_t base = (uint64_t(2) << 61) | (uint64_t(1) << 46) |
                          (uint64_t(64) << 32) | (uint64_t(1) << 16);
    return base | ((uint64_t)(addr >> 4) & 0x3FFF);
}

static __device__ __forceinline__ void mma_f16_ss_cg2(
    uint32_t d, uint64_t ad, uint64_t bd, uint32_t idesc, bool acc)
{
    uint32_t en = acc ? 1u : 0u;
    asm volatile(
        "{\n\t.reg .pred p;\n\t"
        "setp.ne.u32 p, %5, 0;\n\t"
        "tcgen05.mma.cta_group::2.kind::f16 [%0], %1, %2, %3, "
        "{%4, %4, %4, %4, %4, %4, %4, %4}, p;\n\t}"
        :: "r"(d), "l"(ad), "l"(bd), "r"(idesc), "r"(0u), "r"(en) : "memory");
}

#define LDTM32(r, a) \
    asm volatile("tcgen05.ld.sync.aligned.32x32b.x32.b32 " \
        "{%0,%1,%2,%3,%4,%5,%6,%7,%8,%9,%10,%11,%12,%13,%14,%15," \
        "%16,%17,%18,%19,%20,%21,%22,%23,%24,%25,%26,%27,%28,%29,%30,%31}, [%32];" \
        : "=r"((r)[0]),"=r"((r)[1]),"=r"((r)[2]),"=r"((r)[3]),"=r"((r)[4]),"=r"((r)[5]), \
          "=r"((r)[6]),"=r"((r)[7]),"=r"((r)[8]),"=r"((r)[9]),"=r"((r)[10]),"=r"((r)[11]), \
          "=r"((r)[12]),"=r"((r)[13]),"=r"((r)[14]),"=r"((r)[15]),"=r"((r)[16]),"=r"((r)[17]), \
          "=r"((r)[18]),"=r"((r)[19]),"=r"((r)[20]),"=r"((r)[21]),"=r"((r)[22]),"=r"((r)[23]), \
          "=r"((r)[24]),"=r"((r)[25]),"=r"((r)[26]),"=r"((r)[27]),"=r"((r)[28]),"=r"((r)[29]), \
          "=r"((r)[30]),"=r"((r)[31]) : "r"(a))

// one chunk's A+B TMA loads for this rank (both CTAs call; completions -> leader full[st])
static __device__ __forceinline__ void issue_chunk(
    uint32_t sb, const CUtensorMap* tmA, const CUtensorMap* tmB,
    int r, int pair, int rank, bool expect)
{
    const int st = r % NSTAGE;
    const int ti = r >> 4, k = r & 15;
    const int tile = pair + ti * PAIRS;
    const int m = tile & 15, n = tile >> 4;
    const uint32_t dst = sb + st * STAGE_BYTES;
    if (expect) MBAR_EXPECT_TX(sb + SM_FULL(st), TX_BYTES);
    TMA_2D_CG2(dst,         tmA, k * KC, m * 256 + rank * 128, sb + SM_FULL(st));
    TMA_2D_CG2(dst + 16384, tmB, k * KC, n * 256 + rank * 128, sb + SM_FULL(st));
}
#endif  // HAVE_TCGEN05

// ---------- merged prep: fp32 -> fp16 for X and masked W in one launch ----------
static __device__ __forceinline__ uint32_t pack2(float a, float b) {
    __half2 h = __floats2half2_rn(a, b);
    return *reinterpret_cast<uint32_t*>(&h);
}

__global__ void cvt_all_kernel(const float4* __restrict__ x,
                               const float4* __restrict__ w, const float4* __restrict__ m,
                               uint4* __restrict__ ox, uint4* __restrict__ ow,
                               int n8x, int n8w)
{
    int i = blockIdx.x * blockDim.x + threadIdx.x;
    if (i < n8x) {
        float4 a = __ldcs(&x[2*i]);
        float4 b = __ldcs(&x[2*i+1]);
        uint4 r;
        r.x = pack2(a.x, a.y); r.y = pack2(a.z, a.w);
        r.z = pack2(b.x, b.y); r.w = pack2(b.z, b.w);
        ox[i] = r;
    } else if (i < n8x + n8w) {
        int j = i - n8x;
        float4 a = __ldcs(&w[2*j]);   float4 ka = __ldcs(&m[2*j]);
        float4 b = __ldcs(&w[2*j+1]); float4 kb = __ldcs(&m[2*j+1]);
        uint4 r;
        r.x = pack2(a.x*ka.x, a.y*ka.y); r.y = pack2(a.z*ka.z, a.w*ka.w);
        r.z = pack2(b.x*kb.x, b.y*kb.y); r.w = pack2(b.z*kb.z, b.w*kb.w);
        ow[j] = r;
    }
}

// ---------- persistent warp-specialized cg2 GEMM + fused epilogue ----------
// grid = 148 (74 cg2 pairs, 1 CTA/SM), 160 threads:
//   warps 0-3: epilogue (128 threads = 128 M rows of this CTA)
//   warp 4   : thread 128 = TMA producer (+ MMA/commit leader on rank 0)
__global__ void __launch_bounds__(160, 1) __cluster_dims__(2, 1, 1)
fused_gemm(const __grid_constant__ CUtensorMap tmA,
           const __grid_constant__ CUtensorMap tmB,
           const float* __restrict__ bd, const float* __restrict__ Ws,
           const float* __restrict__ bs, float* __restrict__ out)
{
    extern __shared__ uint8_t smem_raw[];
    const uint32_t sraw = smem_u32(smem_raw);
    const uint32_t sb   = (sraw + 1023u) & ~1023u;
    char* sp = (char*)smem_raw + (sb - sraw);

    const int tid  = threadIdx.x;
    const int pair = blockIdx.x >> 1;

#if HAVE_TCGEN05
    uint32_t rank;
    asm("mov.u32 %0, %%cluster_ctarank;" : "=r"(rank));

    int nloc = 0;
    for (int t = pair; t < NTILES; t += PAIRS) nloc++;
    const int chunks = nloc * 16;

    if (tid >= 128) {   // warp 4 allocates 512 TMEM cols for the pair
        asm volatile("tcgen05.alloc.cta_group::2.sync.aligned.shared::cta.b32 [%0], %1;"
                     :: "r"(sb + SM_TM), "r"(512u) : "memory");
        asm volatile("tcgen05.relinquish_alloc_permit.cta_group::2.sync.aligned;");
    }
    if (tid == 0) {
        #pragma unroll
        for (int s = 0; s < NSTAGE; ++s) {
            MBAR_INIT(sb + SM_FULL(s), 1);
            MBAR_INIT(sb + SM_EMPTY(s), 1);
        }
        MBAR_INIT(sb + SM_MD(0), 1);  MBAR_INIT(sb + SM_MD(1), 1);
        MBAR_INIT(sb + SM_ED(0), 256); MBAR_INIT(sb + SM_ED(1), 256);
    }
    __syncthreads();
    uint32_t tmem;
    asm volatile("ld.shared.b32 %0, [%1];" : "=r"(tmem) : "r"(sb + SM_TM));
    CLUSTER_SYNC();   // peer barriers live before cg2 TMA / multicast commits

    if (tid == 128) {
        // prime the pipeline
        for (int s = 0; s < NSTAGE; ++s)
            issue_chunk(sb, &tmA, &tmB, s, pair, (int)rank, rank == 0);

        if (rank == 0) {
            for (int g = 0; g < chunks; ++g) {
                const int st = g % NSTAGE;
                // lagged refill: chunk g+4 reuses stage of chunk g-1 (already committed)
                const int r = g + 4;
                if (g >= 1 && r < chunks) {
                    MBAR_WAIT(sb + SM_EMPTY(r % NSTAGE), ((g - 1) / NSTAGE) & 1);
                    issue_chunk(sb, &tmA, &tmB, r, pair, 0, true);
                }
                const int ti  = g >> 4;
                const int buf = ti & 1;
                if ((g & 15) == 0) {            // TMEM buffer reuse gate
                    const int u = ti >> 1;
                    if (u >= 1) MBAR_WAIT(sb + SM_ED(buf), (u - 1) & 1);
                }
                MBAR_WAIT(sb + SM_FULL(st), (g / NSTAGE) & 1);
                const uint64_t ad  = make_desc(sb + st * STAGE_BYTES);
                const uint64_t bdd = make_desc(sb + st * STAGE_BYTES + 16384);
                #pragma unroll
                for (int k4 = 0; k4 < 4; ++k4)
                    mma_f16_ss_cg2(tmem + buf * 256, ad + 2*k4, bdd + 2*k4,
                                   MMA_IDESC, ((g & 15) | k4) != 0);
                TC_COMMIT_MC_CG2(sb + SM_EMPTY(st), 3);
                if ((g & 15) == 15)
                    TC_COMMIT_MC_CG2(sb + SM_MD(buf), 3);
            }
        } else {
            for (int g = 1; g + 4 < chunks; ++g) {
                const int r = g + 4;
                MBAR_WAIT(sb + SM_EMPTY(r % NSTAGE), ((g - 1) / NSTAGE) & 1);
                issue_chunk(sb, &tmA, &tmB, r, pair, 1, false);
            }
        }
    } else if (tid < 128) {
        const int wid = tid >> 5, lane = tid & 31;
        int ti = 0;
        for (int tile = pair; tile < NTILES; tile += PAIRS, ++ti) {
            const int buf = ti & 1, u = ti >> 1;
            const int n = tile >> 4, m = tile & 15;
            float* bd_s = (float*)(sp + SM_BIAS(buf));
            float* ws_s = bd_s + 256;
            float* bs_s = ws_s + 256;
            {   // stage bias/2nd-layer weights while MMA runs
                const int nb = n * NT;
                bd_s[tid]       = bd[nb + tid];
                bd_s[tid + 128] = bd[nb + tid + 128];
                #pragma unroll
                for (int t = tid; t < NT; t += 128) {
                    int g2 = t >> 4, d2 = t & 15;
                    int nn = n * 16 + g2;
                    ws_s[t] = Ws[(size_t)nn * NSOMA + nn * 16 + d2];
                }
                if (tid < 16) bs_s[tid] = bs[n * 16 + tid];
            }
            asm volatile("bar.sync 1, 128;" ::: "memory");

            MBAR_WAIT(sb + SM_MD(buf), u & 1);
            asm volatile("tcgen05.fence::after_thread_sync;" ::: "memory");

            float acc[16];
            #pragma unroll
            for (int i = 0; i < 16; ++i) acc[i] = 0.f;
            #pragma unroll
            for (int cb = 0; cb < 8; ++cb) {
                uint32_t r[32];
                LDTM32(r, tmem + buf * 256 + cb * 32);
                asm volatile("tcgen05.wait::ld.sync.aligned;" ::: "memory");
                #pragma unroll
                for (int j = 0; j < 32; ++j) {
                    int c = cb * 32 + j;
                    float v = __uint_as_float(r[j]) + bd_s[c];
                    v = v >= 0.f ? v : 0.1f * v;
                    acc[c >> 4] += v * ws_s[c];
                }
            }
            {
                int row = m * 256 + (int)rank * 128 + wid * 32 + lane;
                float* op = out + (size_t)row * NNEUR + n * 16;
                #pragma unroll
                for (int g2 = 0; g2 < 16; ++g2) {
                    float v = acc[g2] + bs_s[g2];
                    op[g2] = v >= 0.f ? v : 0.1f * v;
                }
            }
            MBAR_ARRIVE_LEADER(sb + SM_ED(buf));     // free TMEM buffer for leader
            asm volatile("bar.sync 1, 128;" ::: "memory");
        }
    }

    __syncthreads();
    CLUSTER_SYNC();
    if (tid >= 128) {
        asm volatile("tcgen05.dealloc.cta_group::2.sync.aligned.b32 %0, %1;" :: "r"(tmem), "r"(512u));
    }
    CLUSTER_SYNC();
#else
    // ---------- SIMT fallback (non-'a' compile target; never executed on GB300) ----------
    (void)sp;
    for (int tile = blockIdx.x; tile < NTILES; tile += 148) {
        int m = tile & 15, n = tile >> 4;
        for (int idx = tid; idx < 256 * 16; idx += 160) {
            int rrow = idx >> 4, nl = idx & 15;
            int grow = m * 256 + rrow;
            int neuron = n * 16 + nl;
            float o = 0.f;
            for (int d = 0; d < 16; ++d) {
                int soma = neuron * 16 + d;
                const __half2* wr = (const __half2*)&g_W16[(size_t)soma * K_DIM];
                const __half2* xr = (const __half2*)&g_X16[(size_t)grow * K_DIM];
                float s = 0.f;
                for (int kk = 0; kk < K_DIM / 2; ++kk) {
                    float2 a = __half22float2(xr[kk]);
                    float2 b = __half22float2(wr[kk]);
                    s += a.x * b.x + a.y * b.y;
                }
                s += bd[soma];
                s = s >= 0.f ? s : 0.1f * s;
                o += s * Ws[(size_t)neuron * NSOMA + soma];
            }
            o += bs[neuron];
            o = o >= 0.f ? o : 0.1f * o;
            out[(size_t)grow * NNEUR + neuron] = o;
        }
    }
#endif
}

// ---------- host ----------
typedef CUresult (*EncodeFn)(CUtensorMap*, CUtensorMapDataType, cuuint32_t, void*,
                             const cuuint64_t*, const cuuint64_t*, const cuuint32_t*,
                             const cuuint32_t*, CUtensorMapInterleave, CUtensorMapSwizzle,
                             CUtensorMapL2promotion, CUtensorMapFloatOOBfill);

static void make_map(EncodeFn enc, CUtensorMap* map, void* ptr,
                     uint64_t rows, uint32_t box_rows)
{
    cuuint64_t dims[2]    = {K_DIM, rows};
    cuuint64_t strides[1] = {K_DIM * 2};
    cuuint32_t box[2]     = {KC, box_rows};
    cuuint32_t es[2]      = {1, 1};
    enc(map, CU_TENSOR_MAP_DATA_TYPE_FLOAT16, 2, ptr, dims, strides, box, es,
        CU_TENSOR_MAP_INTERLEAVE_NONE, CU_TENSOR_MAP_SWIZZLE_128B,
        CU_TENSOR_MAP_L2_PROMOTION_L2_128B, CU_TENSOR_MAP_FLOAT_OOB_FILL_NONE);
}

extern "C" void kernel_launch(void* const* d_in, const int* in_sizes, int n_in,
                              void* d_out, int out_size)
{
    const float* x    = (const float*)d_in[0];
    const float* Wd   = (const float*)d_in[1];
    const float* bd   = (const float*)d_in[2];
    const float* Ws   = (const float*)d_in[3];
    const float* bs   = (const float*)d_in[4];
    const float* dmask= (const float*)d_in[5];
    float* out = (float*)d_out;

    void* px; void* pw;
    cudaGetSymbolAddress(&px, g_X16);
    cudaGetSymbolAddress(&pw, g_W16);

    cudaDriverEntryPointQueryResult qr;
    void* fn = nullptr;
    cudaGetDriverEntryPointByVersion("cuTensorMapEncodeTiled", &fn, 12000,
                                     cudaEnableDefault, &qr);
    EncodeFn enc = (EncodeFn)fn;

    CUtensorMap tmA, tmB;
    make_map(enc, &tmA, px, B_DIM, 128);   // A box: 64 x 128
    make_map(enc, &tmB, pw, NSOMA, 128);   // B box: 64 x 128

    cudaFuncSetAttribute(fused_gemm, cudaFuncAttributeMaxDynamicSharedMemorySize, SMEM_BYTES);

    int n8x = B_DIM * K_DIM / 8;     // 524288
    int n8w = NSOMA * K_DIM / 8;     // 2097152
    int total = n8x + n8w;
    cvt_all_kernel<<<(total + 255) / 256, 256>>>((const float4*)x, (const float4*)Wd,
                                                 (const float4*)dmask,
                                                 (uint4*)px, (uint4*)pw, n8x, n8w);
    fused_gemm<<<148, 160, SMEM_BYTES>>>(tmA, tmB, bd, Ws, bs, out);
}

// round 7
// speedup vs baseline: 1.1900x; 1.1900x over previous
#include <cuda_runtime.h>
#include <cuda.h>
#include <cuda_fp16.h>
#include <cstdint>

#define B_DIM  4096
#define K_DIM  1024
#define NSOMA  16384
#define NNEUR  1024

#define NT     256
#define KC     64
#define PAIRS  74
#define NTILES 1024          // 16 m-pairs x 64 n-tiles
#define NSTAGE 5

#define STAGE_BYTES 32768    // A half (16KB) + B half (16KB) per CTA
#define TX_BYTES    65536    // 4 TMA loads (2 per CTA) per chunk into leader barrier

#define SM_TM       163840
#define SM_FULL(s)  (163856 + 8*(s))
#define SM_EMPTY(s) (163896 + 8*(s))
#define SM_MD(b)    (163936 + 8*(b))
#define SM_ED(b)    (163952 + 8*(b))
#define SM_BIAS(b)  (163968 + 2176*(b))
#define SMEM_BYTES  (163968 + 2*2176 + 1024)

// idesc kind::f16 cg2: D=F32(bit4), f16 A/B, N=256, M=256
#define MMA_IDESC ((1u << 4) | ((256 / 8) << 17) | ((256 / 16) << 24))

#if defined(__CUDA_ARCH_FEAT_SM103_ALL) || defined(__CUDA_ARCH_FEAT_SM100_ALL) || defined(__CUDA_ARCH_FEAT_SM101_ALL)
#define HAVE_TCGEN05 1
#else
#define HAVE_TCGEN05 0
#endif

__device__ __align__(1024) __half g_X16[(size_t)B_DIM * K_DIM];
__device__ __align__(1024) __half g_W16[(size_t)NSOMA * K_DIM];

static __device__ __forceinline__ uint32_t smem_u32(const void* p) {
    uint32_t a;
    asm("{ .reg .u64 t; cvta.to.shared.u64 t, %1; cvt.u32.u64 %0, t; }" : "=r"(a) : "l"(p));
    return a;
}

#define MBAR_INIT(a, c) \
    asm volatile("mbarrier.init.shared.b64 [%0], %1;" :: "r"((uint32_t)(a)), "r"((uint32_t)(c)) : "memory")
#define MBAR_EXPECT_TX(a, b) \
    asm volatile("mbarrier.arrive.expect_tx.shared.b64 _, [%0], %1;" :: "r"((uint32_t)(a)), "r"((uint32_t)(b)) : "memory")
#define MBAR_WAIT(a, p) do {                                                     \
    uint32_t _m = (uint32_t)(a), _p = (uint32_t)(p), _d;                         \
    asm volatile("{\n\t.reg .pred q;\n\t"                                        \
        "mbarrier.try_wait.parity.acquire.cta.shared::cta.b64 q, [%1], %2;\n\t"  \
        "selp.b32 %0, 1, 0, q;\n\t}" : "=r"(_d) : "r"(_m), "r"(_p) : "memory");  \
    if (!_d) {                                                                   \
        asm volatile("{\n\t.reg .pred Q;\n\t"                                    \
            "WL_%=:\n\t"                                                         \
            "mbarrier.try_wait.parity.acquire.cta.shared::cta.b64 Q, [%0], %1, 0x989680;\n\t" \
            "@Q bra.uni WD_%=;\n\tbra.uni WL_%=;\n\tWD_%=:\n\t}"                 \
            :: "r"(_m), "r"(_p) : "memory");                                     \
    }                                                                            \
} while (0)

#if HAVE_TCGEN05
#define TMA_2D_CG2(dst, tm, cx, cy, mbar) \
    asm volatile("{\n\t.reg .b32 lb;\n\t" \
                 "and.b32 lb, %4, 0xFEFFFFFF;\n\t" \
                 "cp.async.bulk.tensor.2d.cta_group::2.shared::cluster.global.tile.mbarrier::complete_tx::bytes " \
                 "[%0], [%1, {%2, %3}], [lb];\n\t}" \
                 :: "r"((uint32_t)(dst)), "l"(tm), "r"((int32_t)(cx)), "r"((int32_t)(cy)), \
                    "r"((uint32_t)(mbar)) : "memory")

#define TC_COMMIT_MC_CG2(mbar, mask) \
    asm volatile("tcgen05.commit.cta_group::2.mbarrier::arrive::one.shared::cluster.multicast::cluster.b64 [%0], %1;" \
                 :: "r"((uint32_t)(mbar)), "h"((uint16_t)(mask)) : "memory")

#define MBAR_ARRIVE_LEADER(a) \
    asm volatile("{\n\t.reg .b32 la;\n\tand.b32 la, %0, 0xFEFFFFFF;\n\t" \
                 "mbarrier.arrive.shared::cluster.b64 _, [la];\n\t}" \
                 :: "r"((uint32_t)(a)) : "memory")

#define CLUSTER_SYNC() do { \
    asm volatile("barrier.cluster.arrive.aligned;" ::: "memory"); \
    asm volatile("barrier.cluster.wait.aligned;" ::: "memory"); \
} while (0)

static __device__ __forceinline__ uint64_t make_desc(uint32_t addr) {
    const uint64_t base = (uint64_t(2) << 61) | (uint64_t(1) << 46) |
                          (uint64_t(64) << 32) | (uint64_t(1) << 16);
    return base | ((uint64_t)(addr >> 4) & 0x3FFF);
}

static __device__ __forceinline__ void mma_f16_ss_cg2(
    uint32_t d, uint64_t ad, uint64_t bd, uint32_t idesc, bool acc)
{
    uint32_t en = acc ? 1u : 0u;
    asm volatile(
        "{\n\t.reg .pred p;\n\t"
        "setp.ne.u32 p, %5, 0;\n\t"
        "tcgen05.mma.cta_group::2.kind::f16 [%0], %1, %2, %3, "
        "{%4, %4, %4, %4, %4, %4, %4, %4}, p;\n\t}"
        :: "r"(d), "l"(ad), "l"(bd), "r"(idesc), "r"(0u), "r"(en) : "memory");
}

#define LDTM32(r, a) \
    asm volatile("tcgen05.ld.sync.aligned.32x32b.x32.b32 " \
        "{%0,%1,%2,%3,%4,%5,%6,%7,%8,%9,%10,%11,%12,%13,%14,%15," \
        "%16,%17,%18,%19,%20,%21,%22,%23,%24,%25,%26,%27,%28,%29,%30,%31}, [%32];" \
        : "=r"((r)[0]),"=r"((r)[1]),"=r"((r)[2]),"=r"((r)[3]),"=r"((r)[4]),"=r"((r)[5]), \
          "=r"((r)[6]),"=r"((r)[7]),"=r"((r)[8]),"=r"((r)[9]),"=r"((r)[10]),"=r"((r)[11]), \
          "=r"((r)[12]),"=r"((r)[13]),"=r"((r)[14]),"=r"((r)[15]),"=r"((r)[16]),"=r"((r)[17]), \
          "=r"((r)[18]),"=r"((r)[19]),"=r"((r)[20]),"=r"((r)[21]),"=r"((r)[22]),"=r"((r)[23]), \
          "=r"((r)[24]),"=r"((r)[25]),"=r"((r)[26]),"=r"((r)[27]),"=r"((r)[28]),"=r"((r)[29]), \
          "=r"((r)[30]),"=r"((r)[31]) : "r"(a))

// one chunk's A+B TMA loads for this rank (completions -> pair leader's full[st])
static __device__ __forceinline__ void issue_chunk(
    uint32_t sb, const CUtensorMap* tmA, const CUtensorMap* tmB,
    int r, int pair, int rank, bool expect)
{
    const int st = r % NSTAGE;
    const int ti = r >> 4, k = r & 15;
    const int tile = pair + ti * PAIRS;
    const int m = tile & 15, n = tile >> 4;
    const uint32_t dst = sb + st * STAGE_BYTES;
    if (expect) MBAR_EXPECT_TX(sb + SM_FULL(st), TX_BYTES);
    TMA_2D_CG2(dst,         tmA, k * KC, m * 256 + rank * 128, sb + SM_FULL(st));
    TMA_2D_CG2(dst + 16384, tmB, k * KC, n * 256 + rank * 128, sb + SM_FULL(st));
}
#endif  // HAVE_TCGEN05

// ---------- merged prep: fp32 -> fp16 for X and masked W in one launch ----------
static __device__ __forceinline__ uint32_t pack2(float a, float b) {
    __half2 h = __floats2half2_rn(a, b);
    return *reinterpret_cast<uint32_t*>(&h);
}

__global__ void cvt_all_kernel(const float4* __restrict__ x,
                               const float4* __restrict__ w, const float4* __restrict__ m,
                               uint4* __restrict__ ox, uint4* __restrict__ ow,
                               int n8x, int n8w)
{
    int i = blockIdx.x * blockDim.x + threadIdx.x;
    if (i < n8x) {
        float4 a = __ldcs(&x[2*i]);
        float4 b = __ldcs(&x[2*i+1]);
        uint4 r;
        r.x = pack2(a.x, a.y); r.y = pack2(a.z, a.w);
        r.z = pack2(b.x, b.y); r.w = pack2(b.z, b.w);
        ox[i] = r;
    } else if (i < n8x + n8w) {
        int j = i - n8x;
        float4 a = __ldcs(&w[2*j]);   float4 ka = __ldcs(&m[2*j]);
        float4 b = __ldcs(&w[2*j+1]); float4 kb = __ldcs(&m[2*j+1]);
        uint4 r;
        r.x = pack2(a.x*ka.x, a.y*ka.y); r.y = pack2(a.z*ka.z, a.w*ka.w);
        r.z = pack2(b.x*kb.x, b.y*kb.y); r.w = pack2(b.z*kb.z, b.w*kb.w);
        ow[j] = r;
    }
}

// ---------- persistent warp-specialized cg2 GEMM + fused epilogue ----------
// grid = 148 (74 cg2 pairs, 1 CTA/SM), 160 threads:
//   warps 0-3 : epilogue (128 threads = 128 M rows of this CTA)
//   warp 4    : tid 128 = MMA/commit leader (rank 0 only)
//               tid 129 = TMA producer (both ranks; absorbs EMPTY waits)
__global__ void __launch_bounds__(160, 1) __cluster_dims__(2, 1, 1)
fused_gemm(const __grid_constant__ CUtensorMap tmA,
           const __grid_constant__ CUtensorMap tmB,
           const float* __restrict__ bd, const float* __restrict__ Ws,
           const float* __restrict__ bs, float* __restrict__ out)
{
    extern __shared__ uint8_t smem_raw[];
    const uint32_t sraw = smem_u32(smem_raw);
    const uint32_t sb   = (sraw + 1023u) & ~1023u;
    char* sp = (char*)smem_raw + (sb - sraw);

    const int tid  = threadIdx.x;
    const int pair = blockIdx.x >> 1;

#if HAVE_TCGEN05
    uint32_t rank;
    asm("mov.u32 %0, %%cluster_ctarank;" : "=r"(rank));

    int nloc = 0;
    for (int t = pair; t < NTILES; t += PAIRS) nloc++;
    const int chunks = nloc * 16;

    if (tid >= 128) {   // warp 4 allocates 512 TMEM cols for the pair
        asm volatile("tcgen05.alloc.cta_group::2.sync.aligned.shared::cta.b32 [%0], %1;"
                     :: "r"(sb + SM_TM), "r"(512u) : "memory");
        asm volatile("tcgen05.relinquish_alloc_permit.cta_group::2.sync.aligned;");
    }
    if (tid == 0) {
        #pragma unroll
        for (int s = 0; s < NSTAGE; ++s) {
            MBAR_INIT(sb + SM_FULL(s), 1);
            MBAR_INIT(sb + SM_EMPTY(s), 1);
        }
        MBAR_INIT(sb + SM_MD(0), 1);  MBAR_INIT(sb + SM_MD(1), 1);
        MBAR_INIT(sb + SM_ED(0), 256); MBAR_INIT(sb + SM_ED(1), 256);
    }
    __syncthreads();
    uint32_t tmem;
    asm volatile("ld.shared.b32 %0, [%1];" : "=r"(tmem) : "r"(sb + SM_TM));
    CLUSTER_SYNC();   // peer barriers live before cg2 TMA / multicast commits

    if (tid == 129) {
        // TMA producer: runs up to NSTAGE chunks ahead; absorbs all EMPTY waits
        for (int r = 0; r < chunks; ++r) {
            if (r >= NSTAGE)
                MBAR_WAIT(sb + SM_EMPTY(r % NSTAGE), ((r / NSTAGE) - 1) & 1);
            issue_chunk(sb, &tmA, &tmB, r, pair, (int)rank, rank == 0);
        }
    } else if (tid == 128 && rank == 0) {
        // MMA leader: waits only FULL (TMA-paced) and ED (epilogue-paced)
        for (int g = 0; g < chunks; ++g) {
            const int st  = g % NSTAGE;
            const int ti  = g >> 4;
            const int buf = ti & 1;
            if ((g & 15) == 0) {               // TMEM buffer reuse gate
                const int u = ti >> 1;
                if (u >= 1) MBAR_WAIT(sb + SM_ED(buf), (u - 1) & 1);
            }
            MBAR_WAIT(sb + SM_FULL(st), (g / NSTAGE) & 1);
            const uint64_t ad  = make_desc(sb + st * STAGE_BYTES);
            const uint64_t bdd = make_desc(sb + st * STAGE_BYTES + 16384);
            #pragma unroll
            for (int k4 = 0; k4 < 4; ++k4)
                mma_f16_ss_cg2(tmem + buf * 256, ad + 2*k4, bdd + 2*k4,
                               MMA_IDESC, ((g & 15) | k4) != 0);
            TC_COMMIT_MC_CG2(sb + SM_EMPTY(st), 3);
            if ((g & 15) == 15)
                TC_COMMIT_MC_CG2(sb + SM_MD(buf), 3);
        }
    } else if (tid < 128) {
        const int wid = tid >> 5, lane = tid & 31;
        int ti = 0;
        for (int tile = pair; tile < NTILES; tile += PAIRS, ++ti) {
            const int buf = ti & 1, u = ti >> 1;
            const int n = tile >> 4, m = tile & 15;
            float* bd_s = (float*)(sp + SM_BIAS(buf));
            float* ws_s = bd_s + 256;
            float* bs_s = ws_s + 256;
            {   // stage bias / 2nd-layer weights while MMA runs
                const int nb = n * NT;
                bd_s[tid]       = bd[nb + tid];
                bd_s[tid + 128] = bd[nb + tid + 128];
                #pragma unroll
                for (int t = tid; t < NT; t += 128) {
                    int g2 = t >> 4, d2 = t & 15;
                    int nn = n * 16 + g2;
                    ws_s[t] = Ws[(size_t)nn * NSOMA + nn * 16 + d2];
                }
                if (tid < 16) bs_s[tid] = bs[n * 16 + tid];
            }
            asm volatile("bar.sync 1, 128;" ::: "memory");

            MBAR_WAIT(sb + SM_MD(buf), u & 1);
            asm volatile("tcgen05.fence::after_thread_sync;" ::: "memory");

            float acc[16];
            #pragma unroll
            for (int i = 0; i < 16; ++i) acc[i] = 0.f;
            #pragma unroll
            for (int cb = 0; cb < 8; ++cb) {
                uint32_t r[32];
                LDTM32(r, tmem + buf * 256 + cb * 32);
                asm volatile("tcgen05.wait::ld.sync.aligned;" ::: "memory");
                #pragma unroll
                for (int j = 0; j < 32; ++j) {
                    int c = cb * 32 + j;
                    float v = __uint_as_float(r[j]) + bd_s[c];
                    v = v >= 0.f ? v : 0.1f * v;
                    acc[c >> 4] += v * ws_s[c];
                }
            }
            {
                int row = m * 256 + (int)rank * 128 + wid * 32 + lane;
                float* op = out + (size_t)row * NNEUR + n * 16;
                #pragma unroll
                for (int g2 = 0; g2 < 16; ++g2) {
                    float v = acc[g2] + bs_s[g2];
                    op[g2] = v >= 0.f ? v : 0.1f * v;
                }
            }
            MBAR_ARRIVE_LEADER(sb + SM_ED(buf));     // free TMEM buffer for leader
            asm volatile("bar.sync 1, 128;" ::: "memory");
        }
    }

    __syncthreads();
    CLUSTER_SYNC();
    if (tid >= 128) {
        asm volatile("tcgen05.dealloc.cta_group::2.sync.aligned.b32 %0, %1;" :: "r"(tmem), "r"(512u));
    }
    CLUSTER_SYNC();
#else
    // ---------- SIMT fallback (non-'a' compile target; never executed on GB300) ----------
    (void)sp;
    for (int tile = blockIdx.x; tile < NTILES; tile += 148) {
        int m = tile & 15, n = tile >> 4;
        for (int idx = tid; idx < 256 * 16; idx += 160) {
            int rrow = idx >> 4, nl = idx & 15;
            int grow = m * 256 + rrow;
            int neuron = n * 16 + nl;
            float o = 0.f;
            for (int d = 0; d < 16; ++d) {
                int soma = neuron * 16 + d;
                const __half2* wr = (const __half2*)&g_W16[(size_t)soma * K_DIM];
                const __half2* xr = (const __half2*)&g_X16[(size_t)grow * K_DIM];
                float s = 0.f;
                for (int kk = 0; kk < K_DIM / 2; ++kk) {
                    float2 a = __half22float2(xr[kk]);
                    float2 b = __half22float2(wr[kk]);
                    s += a.x * b.x + a.y * b.y;
                }
                s += bd[soma];
                s = s >= 0.f ? s : 0.1f * s;
                o += s * Ws[(size_t)neuron * NSOMA + soma];
            }
            o += bs[neuron];
            o = o >= 0.f ? o : 0.1f * o;
            out[(size_t)grow * NNEUR + neuron] = o;
        }
    }
#endif
}

// ---------- host ----------
typedef CUresult (*EncodeFn)(CUtensorMap*, CUtensorMapDataType, cuuint32_t, void*,
                             const cuuint64_t*, const cuuint64_t*, const cuuint32_t*,
                             const cuuint32_t*, CUtensorMapInterleave, CUtensorMapSwizzle,
                             CUtensorMapL2promotion, CUtensorMapFloatOOBfill);

static void make_map(EncodeFn enc, CUtensorMap* map, void* ptr,
                     uint64_t rows, uint32_t box_rows)
{
    cuuint64_t dims[2]    = {K_DIM, rows};
    cuuint64_t strides[1] = {K_DIM * 2};
    cuuint32_t box[2]     = {KC, box_rows};
    cuuint32_t es[2]      = {1, 1};
    enc(map, CU_TENSOR_MAP_DATA_TYPE_FLOAT16, 2, ptr, dims, strides, box, es,
        CU_TENSOR_MAP_INTERLEAVE_NONE, CU_TENSOR_MAP_SWIZZLE_128B,
        CU_TENSOR_MAP_L2_PROMOTION_L2_128B, CU_TENSOR_MAP_FLOAT_OOB_FILL_NONE);
}

extern "C" void kernel_launch(void* const* d_in, const int* in_sizes, int n_in,
                              void* d_out, int out_size)
{
    const float* x    = (const float*)d_in[0];
    const float* Wd   = (const float*)d_in[1];
    const float* bd   = (const float*)d_in[2];
    const float* Ws   = (const float*)d_in[3];
    const float* bs   = (const float*)d_in[4];
    const float* dmask= (const float*)d_in[5];
    float* out = (float*)d_out;

    void* px; void* pw;
    cudaGetSymbolAddress(&px, g_X16);
    cudaGetSymbolAddress(&pw, g_W16);

    cudaDriverEntryPointQueryResult qr;
    void* fn = nullptr;
    cudaGetDriverEntryPointByVersion("cuTensorMapEncodeTiled", &fn, 12000,
                                     cudaEnableDefault, &qr);
    EncodeFn enc = (EncodeFn)fn;

    CUtensorMap tmA, tmB;
    make_map(enc, &tmA, px, B_DIM, 128);   // A box: 64 x 128
    make_map(enc, &tmB, pw, NSOMA, 128);   // B box: 64 x 128

    cudaFuncSetAttribute(fused_gemm, cudaFuncAttributeMaxDynamicSharedMemorySize, SMEM_BYTES);

    int n8x = B_DIM * K_DIM / 8;     // 524288
    int n8w = NSOMA * K_DIM / 8;     // 2097152
    int total = n8x + n8w;
    cvt_all_kernel<<<(total + 255) / 256, 256>>>((const float4*)x, (const float4*)Wd,
                                                 (const float4*)dmask,
                                                 (uint4*)px, (uint4*)pw, n8x, n8w);
    fused_gemm<<<148, 160, SMEM_BYTES>>>(tmA, tmB, bd, Ws, bs, out);
}

// round 8
// speedup vs baseline: 1.2785x; 1.0743x over previous
#include <cuda_runtime.h>
#include <cuda.h>
#include <cuda_fp16.h>
#include <cstdint>

#define B_DIM  4096
#define K_DIM  1024
#define NSOMA  16384
#define NNEUR  1024

#define KC     64
#define PAIRS  74
#define NST    512           // super-tiles: 16 m-pairs x 32 n2 (512-wide N)
#define NSTAGE 4

#define STAGE_BYTES 49152    // A(16K) + B0(16K) + B1(16K) per CTA
#define TX_BYTES    98304    // 6 TMA loads (3 per CTA) per chunk

#define SM_TM       196608
#define SM_FULL(s)  (196624 + 8*(s))
#define SM_EMPTY(s) (196656 + 8*(s))
#define SM_MD       196688
#define SM_ED       196696
#define SM_BIAS(b)  (196704 + 4352*(b))   // [2 sec][256] float2 {bd,ws} + [2][16] bs
#define SMEM_BYTES  (196704 + 2*4352 + 1024)

// idesc kind::f16 cg2: D=F32(bit4), f16 A/B, N=256, M=256
#define MMA_IDESC ((1u << 4) | ((256 / 8) << 17) | ((256 / 16) << 24))

#if defined(__CUDA_ARCH_FEAT_SM103_ALL) || defined(__CUDA_ARCH_FEAT_SM100_ALL) || defined(__CUDA_ARCH_FEAT_SM101_ALL)
#define HAVE_TCGEN05 1
#else
#define HAVE_TCGEN05 0
#endif

__device__ __align__(1024) __half g_X16[(size_t)B_DIM * K_DIM];
__device__ __align__(1024) __half g_W16[(size_t)NSOMA * K_DIM];

static __device__ __forceinline__ uint32_t smem_u32(const void* p) {
    uint32_t a;
    asm("{ .reg .u64 t; cvta.to.shared.u64 t, %1; cvt.u32.u64 %0, t; }" : "=r"(a) : "l"(p));
    return a;
}

#define MBAR_INIT(a, c) \
    asm volatile("mbarrier.init.shared.b64 [%0], %1;" :: "r"((uint32_t)(a)), "r"((uint32_t)(c)) : "memory")
#define MBAR_EXPECT_TX(a, b) \
    asm volatile("mbarrier.arrive.expect_tx.shared.b64 _, [%0], %1;" :: "r"((uint32_t)(a)), "r"((uint32_t)(b)) : "memory")
#define MBAR_WAIT(a, p) do {                                                     \
    uint32_t _m = (uint32_t)(a), _p = (uint32_t)(p), _d;                         \
    asm volatile("{\n\t.reg .pred q;\n\t"                                        \
        "mbarrier.try_wait.parity.acquire.cta.shared::cta.b64 q, [%1], %2;\n\t"  \
        "selp.b32 %0, 1, 0, q;\n\t}" : "=r"(_d) : "r"(_m), "r"(_p) : "memory");  \
    if (!_d) {                                                                   \
        asm volatile("{\n\t.reg .pred Q;\n\t"                                    \
            "WL_%=:\n\t"                                                         \
            "mbarrier.try_wait.parity.acquire.cta.shared::cta.b64 Q, [%0], %1, 0x989680;\n\t" \
            "@Q bra.uni WD_%=;\n\tbra.uni WL_%=;\n\tWD_%=:\n\t}"                 \
            :: "r"(_m), "r"(_p) : "memory");                                     \
    }                                                                            \
} while (0)

#if HAVE_TCGEN05
#define TMA_2D_CG2(dst, tm, cx, cy, mbar) \
    asm volatile("{\n\t.reg .b32 lb;\n\t" \
                 "and.b32 lb, %4, 0xFEFFFFFF;\n\t" \
                 "cp.async.bulk.tensor.2d.cta_group::2.shared::cluster.global.tile.mbarrier::complete_tx::bytes " \
                 "[%0], [%1, {%2, %3}], [lb];\n\t}" \
                 :: "r"((uint32_t)(dst)), "l"(tm), "r"((int32_t)(cx)), "r"((int32_t)(cy)), \
                    "r"((uint32_t)(mbar)) : "memory")

#define TC_COMMIT_MC_CG2(mbar, mask) \
    asm volatile("tcgen05.commit.cta_group::2.mbarrier::arrive::one.shared::cluster.multicast::cluster.b64 [%0], %1;" \
                 :: "r"((uint32_t)(mbar)), "h"((uint16_t)(mask)) : "memory")

#define MBAR_ARRIVE_LEADER(a) \
    asm volatile("{\n\t.reg .b32 la;\n\tand.b32 la, %0, 0xFEFFFFFF;\n\t" \
                 "mbarrier.arrive.shared::cluster.b64 _, [la];\n\t}" \
                 :: "r"((uint32_t)(a)) : "memory")

#define CLUSTER_SYNC() do { \
    asm volatile("barrier.cluster.arrive.aligned;" ::: "memory"); \
    asm volatile("barrier.cluster.wait.aligned;" ::: "memory"); \
} while (0)

static __device__ __forceinline__ uint64_t make_desc(uint32_t addr) {
    const uint64_t base = (uint64_t(2) << 61) | (uint64_t(1) << 46) |
                          (uint64_t(64) << 32) | (uint64_t(1) << 16);
    return base | ((uint64_t)(addr >> 4) & 0x3FFF);
}

static __device__ __forceinline__ void mma_f16_ss_cg2(
    uint32_t d, uint64_t ad, uint64_t bd, uint32_t idesc, bool acc)
{
    uint32_t en = acc ? 1u : 0u;
    asm volatile(
        "{\n\t.reg .pred p;\n\t"
        "setp.ne.u32 p, %5, 0;\n\t"
        "tcgen05.mma.cta_group::2.kind::f16 [%0], %1, %2, %3, "
        "{%4, %4, %4, %4, %4, %4, %4, %4}, p;\n\t}"
        :: "r"(d), "l"(ad), "l"(bd), "r"(idesc), "r"(0u), "r"(en) : "memory");
}

#define LDTM32(r, a) \
    asm volatile("tcgen05.ld.sync.aligned.32x32b.x32.b32 " \
        "{%0,%1,%2,%3,%4,%5,%6,%7,%8,%9,%10,%11,%12,%13,%14,%15," \
        "%16,%17,%18,%19,%20,%21,%22,%23,%24,%25,%26,%27,%28,%29,%30,%31}, [%32];" \
        : "=r"((r)[0]),"=r"((r)[1]),"=r"((r)[2]),"=r"((r)[3]),"=r"((r)[4]),"=r"((r)[5]), \
          "=r"((r)[6]),"=r"((r)[7]),"=r"((r)[8]),"=r"((r)[9]),"=r"((r)[10]),"=r"((r)[11]), \
          "=r"((r)[12]),"=r"((r)[13]),"=r"((r)[14]),"=r"((r)[15]),"=r"((r)[16]),"=r"((r)[17]), \
          "=r"((r)[18]),"=r"((r)[19]),"=r"((r)[20]),"=r"((r)[21]),"=r"((r)[22]),"=r"((r)[23]), \
          "=r"((r)[24]),"=r"((r)[25]),"=r"((r)[26]),"=r"((r)[27]),"=r"((r)[28]),"=r"((r)[29]), \
          "=r"((r)[30]),"=r"((r)[31]) : "r"(a))

// chunk r: A(m,k) + B0(n0,k) + B1(n1,k) halves for this rank -> leader full[st]
static __device__ __forceinline__ void issue_chunk(
    uint32_t sb, const CUtensorMap* tmA, const CUtensorMap* tmB,
    int r, int pair, int rank, bool expect)
{
    const int st = r & 3;
    const int ti = r >> 4, k = r & 15;
    const int s  = pair + ti * PAIRS;          // super-tile
    const int m  = s & 15, n2 = s >> 4;
    const uint32_t dst = sb + st * STAGE_BYTES;
    if (expect) MBAR_EXPECT_TX(sb + SM_FULL(st), TX_BYTES);
    TMA_2D_CG2(dst,         tmA, k * KC, m * 256 + rank * 128,        sb + SM_FULL(st));
    TMA_2D_CG2(dst + 16384, tmB, k * KC, n2 * 512 + rank * 128,       sb + SM_FULL(st));
    TMA_2D_CG2(dst + 32768, tmB, k * KC, n2 * 512 + 256 + rank * 128, sb + SM_FULL(st));
}
#endif  // HAVE_TCGEN05

// ---------- merged prep: fp32 -> fp16 for X and masked W ----------
static __device__ __forceinline__ uint32_t pack2(float a, float b) {
    __half2 h = __floats2half2_rn(a, b);
    return *reinterpret_cast<uint32_t*>(&h);
}

__global__ void cvt_all_kernel(const float4* __restrict__ x,
                               const float4* __restrict__ w, const float4* __restrict__ m,
                               uint4* __restrict__ ox, uint4* __restrict__ ow,
                               int n8x, int n8w)
{
    int i = blockIdx.x * blockDim.x + threadIdx.x;
    if (i < n8x) {
        float4 a = __ldcs(&x[2*i]);
        float4 b = __ldcs(&x[2*i+1]);
        uint4 r;
        r.x = pack2(a.x, a.y); r.y = pack2(a.z, a.w);
        r.z = pack2(b.x, b.y); r.w = pack2(b.z, b.w);
        ox[i] = r;
    } else if (i < n8x + n8w) {
        int j = i - n8x;
        float4 a = __ldcs(&w[2*j]);   float4 ka = __ldcs(&m[2*j]);
        float4 b = __ldcs(&w[2*j+1]); float4 kb = __ldcs(&m[2*j+1]);
        uint4 r;
        r.x = pack2(a.x*ka.x, a.y*ka.y); r.y = pack2(a.z*ka.z, a.w*ka.w);
        r.z = pack2(b.x*kb.x, b.y*kb.y); r.w = pack2(b.z*kb.z, b.w*kb.w);
        ow[j] = r;
    }
}

// ---------- persistent cg2 GEMM, 256x512 super-tiles, A shared across N halves ----------
// grid = 148 (74 pairs), 288 threads:
//   warps 0-3 : epilogue buf0 (128 threads = this CTA's 128 rows, n-tile 2*n2)
//   warps 4-7 : epilogue buf1 (same rows, n-tile 2*n2+1)
//   warp 8    : tid 256 = MMA leader (rank 0), tid 257 = TMA producer (both ranks)
__global__ void __launch_bounds__(288, 1) __cluster_dims__(2, 1, 1)
fused_gemm(const __grid_constant__ CUtensorMap tmA,
           const __grid_constant__ CUtensorMap tmB,
           const float* __restrict__ bd, const float* __restrict__ Ws,
           const float* __restrict__ bs, float* __restrict__ out)
{
    extern __shared__ uint8_t smem_raw[];
    const uint32_t sraw = smem_u32(smem_raw);
    const uint32_t sb   = (sraw + 1023u) & ~1023u;
    char* sp = (char*)smem_raw + (sb - sraw);

    const int tid  = threadIdx.x;
    const int pair = blockIdx.x >> 1;

#if HAVE_TCGEN05
    uint32_t rank;
    asm("mov.u32 %0, %%cluster_ctarank;" : "=r"(rank));

    int nloc = 0;
    for (int t = pair; t < NST; t += PAIRS) nloc++;
    const int chunks = nloc * 16;

    if (tid >= 256) {   // warp 8 allocates 512 TMEM cols for the pair
        asm volatile("tcgen05.alloc.cta_group::2.sync.aligned.shared::cta.b32 [%0], %1;"
                     :: "r"(sb + SM_TM), "r"(512u) : "memory");
        asm volatile("tcgen05.relinquish_alloc_permit.cta_group::2.sync.aligned;");
    }
    if (tid == 0) {
        #pragma unroll
        for (int s = 0; s < NSTAGE; ++s) {
            MBAR_INIT(sb + SM_FULL(s), 1);
            MBAR_INIT(sb + SM_EMPTY(s), 1);
        }
        MBAR_INIT(sb + SM_MD, 1);
        MBAR_INIT(sb + SM_ED, 512);   // 256 epi threads x 2 CTAs
    }
    __syncthreads();
    uint32_t tmem;
    asm volatile("ld.shared.b32 %0, [%1];" : "=r"(tmem) : "r"(sb + SM_TM));
    CLUSTER_SYNC();   // peer barriers live before cg2 TMA / multicast commits

    if (tid == 257) {
        // TMA producer: up to 4 chunks ahead; absorbs all EMPTY waits
        for (int r = 0; r < chunks; ++r) {
            if (r >= NSTAGE)
                MBAR_WAIT(sb + SM_EMPTY(r & 3), ((r >> 2) - 1) & 1);
            issue_chunk(sb, &tmA, &tmB, r, pair, (int)rank, rank == 0);
        }
    } else if (tid == 256 && rank == 0) {
        // MMA leader: FULL (TMA-paced) + ED (epilogue-paced) waits only
        for (int g = 0; g < chunks; ++g) {
            const int st = g & 3;
            if ((g & 15) == 0) {
                const int u = g >> 4;
                if (u >= 1) MBAR_WAIT(sb + SM_ED, (u - 1) & 1);
            }
            MBAR_WAIT(sb + SM_FULL(st), (g >> 2) & 1);
            const uint64_t ad  = make_desc(sb + st * STAGE_BYTES);
            const uint64_t b0d = make_desc(sb + st * STAGE_BYTES + 16384);
            const uint64_t b1d = make_desc(sb + st * STAGE_BYTES + 32768);
            const bool first = (g & 15) == 0;
            #pragma unroll
            for (int k4 = 0; k4 < 4; ++k4)
                mma_f16_ss_cg2(tmem,       ad + 2*k4, b0d + 2*k4, MMA_IDESC, !(first && k4 == 0));
            #pragma unroll
            for (int k4 = 0; k4 < 4; ++k4)
                mma_f16_ss_cg2(tmem + 256, ad + 2*k4, b1d + 2*k4, MMA_IDESC, !(first && k4 == 0));
            TC_COMMIT_MC_CG2(sb + SM_EMPTY(st), 3);
            if ((g & 15) == 15)
                TC_COMMIT_MC_CG2(sb + SM_MD, 3);
        }
    } else if (tid < 256) {
        const int buf  = tid >> 7;           // 0: n-tile 2*n2, 1: n-tile 2*n2+1
        const int rloc = tid & 127;
        int u = 0;
        for (int s = pair; s < NST; s += PAIRS, ++u) {
            const int m = s & 15, n2 = s >> 4;
            const int bb = u & 1;
            float2* bw  = (float2*)(sp + SM_BIAS(bb));        // [2][256] {bd, ws}
            float*  bss = (float*)(sp + SM_BIAS(bb) + 4096);  // [2][16]
            {   // stage both sections' bias data while MMAs run
                #pragma unroll
                for (int sec = 0; sec < 2; ++sec) {
                    const int nt = n2 * 2 + sec;
                    const int c  = tid;          // tid < 256
                    const int nn = nt * 16 + (c >> 4), d = c & 15;
                    float2 v;
                    v.x = bd[nt * 256 + c];
                    v.y = Ws[(size_t)nn * NSOMA + nn * 16 + d];
                    bw[sec * 256 + c] = v;
                }
                if (tid < 32) {
                    const int sec = tid >> 4;
                    bss[tid] = bs[(n2 * 2 + sec) * 16 + (tid & 15)];
                }
            }
            asm volatile("bar.sync 1, 256;" ::: "memory");

            MBAR_WAIT(sb + SM_MD, u & 1);
            asm volatile("tcgen05.fence::after_thread_sync;" ::: "memory");

            float acc[16];
            #pragma unroll
            for (int i = 0; i < 16; ++i) acc[i] = 0.f;
            #pragma unroll
            for (int cb = 0; cb < 8; ++cb) {
                uint32_t r[32];
                LDTM32(r, tmem + buf * 256 + cb * 32);
                asm volatile("tcgen05.wait::ld.sync.aligned;" ::: "memory");
                #pragma unroll
                for (int j = 0; j < 32; ++j) {
                    int c = cb * 32 + j;
                    float2 p = bw[buf * 256 + c];
                    float v = __uint_as_float(r[j]) + p.x;
                    v = fmaxf(v, 0.1f * v);     // leaky (slope<1)
                    acc[c >> 4] += v * p.y;
                }
            }
            {
                const int row = m * 256 + (int)rank * 128 + rloc;
                float* op = out + (size_t)row * NNEUR + (n2 * 2 + buf) * 16;
                #pragma unroll
                for (int g2 = 0; g2 < 16; ++g2) {
                    float v = acc[g2] + bss[buf * 16 + g2];
                    op[g2] = fmaxf(v, 0.1f * v);
                }
            }
            MBAR_ARRIVE_LEADER(sb + SM_ED);   // free TMEM for the leader
            asm volatile("bar.sync 1, 256;" ::: "memory");
        }
    }

    __syncthreads();
    CLUSTER_SYNC();
    if (tid >= 256) {
        asm volatile("tcgen05.dealloc.cta_group::2.sync.aligned.b32 %0, %1;" :: "r"(tmem), "r"(512u));
    }
    CLUSTER_SYNC();
#else
    // ---------- SIMT fallback (non-'a' compile target; never executed on GB300) ----------
    (void)sp;
    for (int tile = blockIdx.x; tile < 1024; tile += 148) {
        int m = tile & 15, n = tile >> 4;
        for (int idx = tid; idx < 256 * 16; idx += 288) {
            int rrow = idx >> 4, nl = idx & 15;
            int grow = m * 256 + rrow;
            int neuron = n * 16 + nl;
            float o = 0.f;
            for (int d = 0; d < 16; ++d) {
                int soma = neuron * 16 + d;
                const __half2* wr = (const __half2*)&g_W16[(size_t)soma * K_DIM];
                const __half2* xr = (const __half2*)&g_X16[(size_t)grow * K_DIM];
                float s = 0.f;
                for (int kk = 0; kk < K_DIM / 2; ++kk) {
                    float2 a = __half22float2(xr[kk]);
                    float2 b = __half22float2(wr[kk]);
                    s += a.x * b.x + a.y * b.y;
                }
                s += bd[soma];
                s = s >= 0.f ? s : 0.1f * s;
                o += s * Ws[(size_t)neuron * NSOMA + soma];
            }
            o += bs[neuron];
            o = o >= 0.f ? o : 0.1f * o;
            out[(size_t)grow * NNEUR + neuron] = o;
        }
    }
#endif
}

// ---------- host ----------
typedef CUresult (*EncodeFn)(CUtensorMap*, CUtensorMapDataType, cuuint32_t, void*,
                             const cuuint64_t*, const cuuint64_t*, const cuuint32_t*,
                             const cuuint32_t*, CUtensorMapInterleave, CUtensorMapSwizzle,
                             CUtensorMapL2promotion, CUtensorMapFloatOOBfill);

static void make_map(EncodeFn enc, CUtensorMap* map, void* ptr,
                     uint64_t rows, uint32_t box_rows)
{
    cuuint64_t dims[2]    = {K_DIM, rows};
    cuuint64_t strides[1] = {K_DIM * 2};
    cuuint32_t box[2]     = {KC, box_rows};
    cuuint32_t es[2]      = {1, 1};
    enc(map, CU_TENSOR_MAP_DATA_TYPE_FLOAT16, 2, ptr, dims, strides, box, es,
        CU_TENSOR_MAP_INTERLEAVE_NONE, CU_TENSOR_MAP_SWIZZLE_128B,
        CU_TENSOR_MAP_L2_PROMOTION_L2_128B, CU_TENSOR_MAP_FLOAT_OOB_FILL_NONE);
}

extern "C" void kernel_launch(void* const* d_in, const int* in_sizes, int n_in,
                              void* d_out, int out_size)
{
    const float* x    = (const float*)d_in[0];
    const float* Wd   = (const float*)d_in[1];
    const float* bd   = (const float*)d_in[2];
    const float* Ws   = (const float*)d_in[3];
    const float* bs   = (const float*)d_in[4];
    const float* dmask= (const float*)d_in[5];
    float* out = (float*)d_out;

    void* px; void* pw;
    cudaGetSymbolAddress(&px, g_X16);
    cudaGetSymbolAddress(&pw, g_W16);

    cudaDriverEntryPointQueryResult qr;
    void* fn = nullptr;
    cudaGetDriverEntryPointByVersion("cuTensorMapEncodeTiled", &fn, 12000,
                                     cudaEnableDefault, &qr);
    EncodeFn enc = (EncodeFn)fn;

    CUtensorMap tmA, tmB;
    make_map(enc, &tmA, px, B_DIM, 128);   // A box: 64 x 128
    make_map(enc, &tmB, pw, NSOMA, 128);   // B box: 64 x 128

    cudaFuncSetAttribute(fused_gemm, cudaFuncAttributeMaxDynamicSharedMemorySize, SMEM_BYTES);

    int n8x = B_DIM * K_DIM / 8;     // 524288
    int n8w = NSOMA * K_DIM / 8;     // 2097152
    int total = n8x + n8w;
    cvt_all_kernel<<<(total + 255) / 256, 256>>>((const float4*)x, (const float4*)Wd,
                                                 (const float4*)dmask,
                                                 (uint4*)px, (uint4*)pw, n8x, n8w);
    fused_gemm<<<148, 288, SMEM_BYTES>>>(tmA, tmB, bd, Ws, bs, out);
}

// round 9
// speedup vs baseline: 1.3426x; 1.0502x over previous
#include <cuda_runtime.h>
#include <cuda.h>
#include <cuda_fp16.h>
#include <cstdint>

#define B_DIM  4096
#define K_DIM  1024
#define NSOMA  16384
#define NNEUR  1024

#define KC     64
#define PAIRS  74
#define NST    512           // super-tiles: 16 m-pairs x 32 n2 (512-wide N)
#define NSTAGE 4

#define STAGE_BYTES 49152    // A(16K) + B0(16K) + B1(16K) per CTA
#define TX_BYTES    98304    // 6 TMA loads (3 per CTA) per chunk

#define SM_TM       196608
#define SM_FULL(s)  (196624 + 8*(s))
#define SM_EMPTY(s) (196656 + 8*(s))
#define SM_MD       196688
#define SM_ED       196696
#define SM_BIAS(b)  (196704 + 4352*(b))   // [2 sec][256] float2 {bd,ws} + [2][16] bs
#define SMEM_BYTES  (196704 + 2*4352 + 1024)

// idesc kind::f16 cg2: D=F32(bit4), f16 A/B, N=256, M=256
#define MMA_IDESC ((1u << 4) | ((256 / 8) << 17) | ((256 / 16) << 24))

#if defined(__CUDA_ARCH_FEAT_SM103_ALL) || defined(__CUDA_ARCH_FEAT_SM100_ALL) || defined(__CUDA_ARCH_FEAT_SM101_ALL)
#define HAVE_TCGEN05 1
#else
#define HAVE_TCGEN05 0
#endif

__device__ __align__(1024) __half g_X16[(size_t)B_DIM * K_DIM];
__device__ __align__(1024) __half g_W16[(size_t)NSOMA * K_DIM];

static __device__ __forceinline__ uint32_t smem_u32(const void* p) {
    uint32_t a;
    asm("{ .reg .u64 t; cvta.to.shared.u64 t, %1; cvt.u32.u64 %0, t; }" : "=r"(a) : "l"(p));
    return a;
}

#define MBAR_INIT(a, c) \
    asm volatile("mbarrier.init.shared.b64 [%0], %1;" :: "r"((uint32_t)(a)), "r"((uint32_t)(c)) : "memory")
#define MBAR_EXPECT_TX(a, b) \
    asm volatile("mbarrier.arrive.expect_tx.shared.b64 _, [%0], %1;" :: "r"((uint32_t)(a)), "r"((uint32_t)(b)) : "memory")
#define MBAR_WAIT(a, p) do {                                                     \
    uint32_t _m = (uint32_t)(a), _p = (uint32_t)(p), _d;                         \
    asm volatile("{\n\t.reg .pred q;\n\t"                                        \
        "mbarrier.try_wait.parity.acquire.cta.shared::cta.b64 q, [%1], %2;\n\t"  \
        "selp.b32 %0, 1, 0, q;\n\t}" : "=r"(_d) : "r"(_m), "r"(_p) : "memory");  \
    if (!_d) {                                                                   \
        asm volatile("{\n\t.reg .pred Q;\n\t"                                    \
            "WL_%=:\n\t"                                                         \
            "mbarrier.try_wait.parity.acquire.cta.shared::cta.b64 Q, [%0], %1, 0x989680;\n\t" \
            "@Q bra.uni WD_%=;\n\tbra.uni WL_%=;\n\tWD_%=:\n\t}"                 \
            :: "r"(_m), "r"(_p) : "memory");                                     \
    }                                                                            \
} while (0)

#if HAVE_TCGEN05
#define TMA_2D_CG2(dst, tm, cx, cy, mbar) \
    asm volatile("{\n\t.reg .b32 lb;\n\t" \
                 "and.b32 lb, %4, 0xFEFFFFFF;\n\t" \
                 "cp.async.bulk.tensor.2d.cta_group::2.shared::cluster.global.tile.mbarrier::complete_tx::bytes " \
                 "[%0], [%1, {%2, %3}], [lb];\n\t}" \
                 :: "r"((uint32_t)(dst)), "l"(tm), "r"((int32_t)(cx)), "r"((int32_t)(cy)), \
                    "r"((uint32_t)(mbar)) : "memory")

#define TC_COMMIT_MC_CG2(mbar, mask) \
    asm volatile("tcgen05.commit.cta_group::2.mbarrier::arrive::one.shared::cluster.multicast::cluster.b64 [%0], %1;" \
                 :: "r"((uint32_t)(mbar)), "h"((uint16_t)(mask)) : "memory")

#define MBAR_ARRIVE_LEADER(a) \
    asm volatile("{\n\t.reg .b32 la;\n\tand.b32 la, %0, 0xFEFFFFFF;\n\t" \
                 "mbarrier.arrive.shared::cluster.b64 _, [la];\n\t}" \
                 :: "r"((uint32_t)(a)) : "memory")

#define CLUSTER_SYNC() do { \
    asm volatile("barrier.cluster.arrive.aligned;" ::: "memory"); \
    asm volatile("barrier.cluster.wait.aligned;" ::: "memory"); \
} while (0)

static __device__ __forceinline__ uint64_t make_desc(uint32_t addr) {
    const uint64_t base = (uint64_t(2) << 61) | (uint64_t(1) << 46) |
                          (uint64_t(64) << 32) | (uint64_t(1) << 16);
    return base | ((uint64_t)(addr >> 4) & 0x3FFF);
}

static __device__ __forceinline__ void mma_f16_ss_cg2(
    uint32_t d, uint64_t ad, uint64_t bd, uint32_t idesc, bool acc)
{
    uint32_t en = acc ? 1u : 0u;
    asm volatile(
        "{\n\t.reg .pred p;\n\t"
        "setp.ne.u32 p, %5, 0;\n\t"
        "tcgen05.mma.cta_group::2.kind::f16 [%0], %1, %2, %3, "
        "{%4, %4, %4, %4, %4, %4, %4, %4}, p;\n\t}"
        :: "r"(d), "l"(ad), "l"(bd), "r"(idesc), "r"(0u), "r"(en) : "memory");
}

#define LDTM32(r, a) \
    asm volatile("tcgen05.ld.sync.aligned.32x32b.x32.b32 " \
        "{%0,%1,%2,%3,%4,%5,%6,%7,%8,%9,%10,%11,%12,%13,%14,%15," \
        "%16,%17,%18,%19,%20,%21,%22,%23,%24,%25,%26,%27,%28,%29,%30,%31}, [%32];" \
        : "=r"((r)[0]),"=r"((r)[1]),"=r"((r)[2]),"=r"((r)[3]),"=r"((r)[4]),"=r"((r)[5]), \
          "=r"((r)[6]),"=r"((r)[7]),"=r"((r)[8]),"=r"((r)[9]),"=r"((r)[10]),"=r"((r)[11]), \
          "=r"((r)[12]),"=r"((r)[13]),"=r"((r)[14]),"=r"((r)[15]),"=r"((r)[16]),"=r"((r)[17]), \
          "=r"((r)[18]),"=r"((r)[19]),"=r"((r)[20]),"=r"((r)[21]),"=r"((r)[22]),"=r"((r)[23]), \
          "=r"((r)[24]),"=r"((r)[25]),"=r"((r)[26]),"=r"((r)[27]),"=r"((r)[28]),"=r"((r)[29]), \
          "=r"((r)[30]),"=r"((r)[31]) : "r"(a))

#define TC_WAIT_LD() asm volatile("tcgen05.wait::ld.sync.aligned;" ::: "memory")

// chunk r: A(m,k) + B0(n0,k) + B1(n1,k) halves for this rank -> leader full[st]
static __device__ __forceinline__ void issue_chunk(
    uint32_t sb, const CUtensorMap* tmA, const CUtensorMap* tmB,
    int r, int pair, int rank, bool expect)
{
    const int st = r & 3;
    const int ti = r >> 4, k = r & 15;
    const int s  = pair + ti * PAIRS;          // super-tile
    const int m  = s & 15, n2 = s >> 4;
    const uint32_t dst = sb + st * STAGE_BYTES;
    if (expect) MBAR_EXPECT_TX(sb + SM_FULL(st), TX_BYTES);
    TMA_2D_CG2(dst,         tmA, k * KC, m * 256 + rank * 128,        sb + SM_FULL(st));
    TMA_2D_CG2(dst + 16384, tmB, k * KC, n2 * 512 + rank * 128,       sb + SM_FULL(st));
    TMA_2D_CG2(dst + 32768, tmB, k * KC, n2 * 512 + 256 + rank * 128, sb + SM_FULL(st));
}
#endif  // HAVE_TCGEN05

// ---------- merged prep: fp32 -> fp16 for X and masked W ----------
static __device__ __forceinline__ uint32_t pack2(float a, float b) {
    __half2 h = __floats2half2_rn(a, b);
    return *reinterpret_cast<uint32_t*>(&h);
}

__global__ void cvt_all_kernel(const float4* __restrict__ x,
                               const float4* __restrict__ w, const float4* __restrict__ m,
                               uint4* __restrict__ ox, uint4* __restrict__ ow,
                               int n8x, int n8w)
{
    int i = blockIdx.x * blockDim.x + threadIdx.x;
    if (i < n8x) {
        float4 a = __ldcs(&x[2*i]);
        float4 b = __ldcs(&x[2*i+1]);
        uint4 r;
        r.x = pack2(a.x, a.y); r.y = pack2(a.z, a.w);
        r.z = pack2(b.x, b.y); r.w = pack2(b.z, b.w);
        ox[i] = r;
    } else if (i < n8x + n8w) {
        int j = i - n8x;
        float4 a = __ldcs(&w[2*j]);   float4 ka = __ldcs(&m[2*j]);
        float4 b = __ldcs(&w[2*j+1]); float4 kb = __ldcs(&m[2*j+1]);
        uint4 r;
        r.x = pack2(a.x*ka.x, a.y*ka.y); r.y = pack2(a.z*ka.z, a.w*ka.w);
        r.z = pack2(b.x*kb.x, b.y*kb.y); r.w = pack2(b.z*kb.z, b.w*kb.w);
        ow[j] = r;
    }
}

// ---------- persistent cg2 GEMM, 256x512 super-tiles, A shared across N halves ----------
// grid = 148 (74 pairs), 288 threads:
//   warps 0-3 : epilogue buf0 (128 threads = this CTA's 128 rows, n-tile 2*n2)
//   warps 4-7 : epilogue buf1 (same rows, n-tile 2*n2+1)
//   warp 8    : tid 256 = MMA leader (rank 0), tid 257 = TMA producer (both ranks)
__global__ void __launch_bounds__(288, 1) __cluster_dims__(2, 1, 1)
fused_gemm(const __grid_constant__ CUtensorMap tmA,
           const __grid_constant__ CUtensorMap tmB,
           const float* __restrict__ bd, const float* __restrict__ Ws,
           const float* __restrict__ bs, float* __restrict__ out)
{
    extern __shared__ uint8_t smem_raw[];
    const uint32_t sraw = smem_u32(smem_raw);
    const uint32_t sb   = (sraw + 1023u) & ~1023u;
    char* sp = (char*)smem_raw + (sb - sraw);

    const int tid  = threadIdx.x;
    const int pair = blockIdx.x >> 1;

#if HAVE_TCGEN05
    uint32_t rank;
    asm("mov.u32 %0, %%cluster_ctarank;" : "=r"(rank));

    int nloc = 0;
    for (int t = pair; t < NST; t += PAIRS) nloc++;
    const int chunks = nloc * 16;

    if (tid >= 256) {   // warp 8 allocates 512 TMEM cols for the pair
        asm volatile("tcgen05.alloc.cta_group::2.sync.aligned.shared::cta.b32 [%0], %1;"
                     :: "r"(sb + SM_TM), "r"(512u) : "memory");
        asm volatile("tcgen05.relinquish_alloc_permit.cta_group::2.sync.aligned;");
    }
    if (tid == 0) {
        #pragma unroll
        for (int s = 0; s < NSTAGE; ++s) {
            MBAR_INIT(sb + SM_FULL(s), 1);
            MBAR_INIT(sb + SM_EMPTY(s), 1);
        }
        MBAR_INIT(sb + SM_MD, 1);
        MBAR_INIT(sb + SM_ED, 512);   // 256 epi threads x 2 CTAs
    }
    __syncthreads();
    uint32_t tmem;
    asm volatile("ld.shared.b32 %0, [%1];" : "=r"(tmem) : "r"(sb + SM_TM));
    CLUSTER_SYNC();   // peer barriers live before cg2 TMA / multicast commits

    if (tid == 257) {
        // TMA producer: up to 4 chunks ahead; absorbs all EMPTY waits
        for (int r = 0; r < chunks; ++r) {
            if (r >= NSTAGE)
                MBAR_WAIT(sb + SM_EMPTY(r & 3), ((r >> 2) - 1) & 1);
            issue_chunk(sb, &tmA, &tmB, r, pair, (int)rank, rank == 0);
        }
    } else if (tid == 256 && rank == 0) {
        // MMA leader: FULL (TMA-paced) + ED (epilogue-paced) waits only
        for (int g = 0; g < chunks; ++g) {
            const int st = g & 3;
            if ((g & 15) == 0) {
                const int u = g >> 4;
                if (u >= 1) MBAR_WAIT(sb + SM_ED, (u - 1) & 1);
            }
            MBAR_WAIT(sb + SM_FULL(st), (g >> 2) & 1);
            const uint64_t ad  = make_desc(sb + st * STAGE_BYTES);
            const uint64_t b0d = make_desc(sb + st * STAGE_BYTES + 16384);
            const uint64_t b1d = make_desc(sb + st * STAGE_BYTES + 32768);
            const bool first = (g & 15) == 0;
            #pragma unroll
            for (int k4 = 0; k4 < 4; ++k4)
                mma_f16_ss_cg2(tmem,       ad + 2*k4, b0d + 2*k4, MMA_IDESC, !(first && k4 == 0));
            #pragma unroll
            for (int k4 = 0; k4 < 4; ++k4)
                mma_f16_ss_cg2(tmem + 256, ad + 2*k4, b1d + 2*k4, MMA_IDESC, !(first && k4 == 0));
            TC_COMMIT_MC_CG2(sb + SM_EMPTY(st), 3);
            if ((g & 15) == 15)
                TC_COMMIT_MC_CG2(sb + SM_MD, 3);
        }
    } else if (tid < 256) {
        const int buf  = tid >> 7;           // 0: n-tile 2*n2, 1: n-tile 2*n2+1
        const int rloc = tid & 127;
        int u = 0;
        for (int s = pair; s < NST; s += PAIRS, ++u) {
            const int m = s & 15, n2 = s >> 4;
            const int bb = u & 1;
            float2* bw  = (float2*)(sp + SM_BIAS(bb));        // [2][256] {bd, ws}
            float*  bss = (float*)(sp + SM_BIAS(bb) + 4096);  // [2][16]
            {   // stage both sections' bias data while MMAs run
                #pragma unroll
                for (int sec = 0; sec < 2; ++sec) {
                    const int nt = n2 * 2 + sec;
                    const int c  = tid;          // tid < 256
                    const int nn = nt * 16 + (c >> 4), d = c & 15;
                    float2 v;
                    v.x = bd[nt * 256 + c];
                    v.y = Ws[(size_t)nn * NSOMA + nn * 16 + d];
                    bw[sec * 256 + c] = v;
                }
                if (tid < 32) {
                    const int sec = tid >> 4;
                    bss[tid] = bs[(n2 * 2 + sec) * 16 + (tid & 15)];
                }
            }
            asm volatile("bar.sync 1, 256;" ::: "memory");

            MBAR_WAIT(sb + SM_MD, u & 1);
            asm volatile("tcgen05.fence::after_thread_sync;" ::: "memory");

            // -------- software-pipelined LDTM + compute --------
            const uint32_t tb = tmem + buf * 256;
            float acc[16];
            #pragma unroll
            for (int i = 0; i < 16; ++i) acc[i] = 0.f;

            uint32_t ra[32], rb[32];
            LDTM32(ra, tb);
            TC_WAIT_LD();
            #pragma unroll
            for (int cb = 0; cb < 8; ++cb) {
                uint32_t* cur = (cb & 1) ? rb : ra;
                uint32_t* nxt = (cb & 1) ? ra : rb;
                if (cb < 7) LDTM32(nxt, tb + (cb + 1) * 32);   // async: hides under compute
                #pragma unroll
                for (int j = 0; j < 32; ++j) {
                    int c = cb * 32 + j;
                    float2 p = bw[buf * 256 + c];
                    float v = __uint_as_float(cur[j]) + p.x;
                    v = fmaxf(v, 0.1f * v);     // leaky (slope<1)
                    acc[c >> 4] += v * p.y;
                }
                if (cb < 7) TC_WAIT_LD();
            }
            // all TMEM reads retired -> release TMEM before the gmem stores
            asm volatile("tcgen05.fence::before_thread_sync;" ::: "memory");
            MBAR_ARRIVE_LEADER(sb + SM_ED);
            {
                const int row = m * 256 + (int)rank * 128 + rloc;
                float* op = out + (size_t)row * NNEUR + (n2 * 2 + buf) * 16;
                #pragma unroll
                for (int g2 = 0; g2 < 16; ++g2) {
                    float v = acc[g2] + bss[buf * 16 + g2];
                    op[g2] = fmaxf(v, 0.1f * v);
                }
            }
            asm volatile("bar.sync 1, 256;" ::: "memory");
        }
    }

    __syncthreads();
    CLUSTER_SYNC();
    if (tid >= 256) {
        asm volatile("tcgen05.dealloc.cta_group::2.sync.aligned.b32 %0, %1;" :: "r"(tmem), "r"(512u));
    }
    CLUSTER_SYNC();
#else
    // ---------- SIMT fallback (non-'a' compile target; never executed on GB300) ----------
    (void)sp;
    for (int tile = blockIdx.x; tile < 1024; tile += 148) {
        int m = tile & 15, n = tile >> 4;
        for (int idx = tid; idx < 256 * 16; idx += 288) {
            int rrow = idx >> 4, nl = idx & 15;
            int grow = m * 256 + rrow;
            int neuron = n * 16 + nl;
            float o = 0.f;
            for (int d = 0; d < 16; ++d) {
                int soma = neuron * 16 + d;
                const __half2* wr = (const __half2*)&g_W16[(size_t)soma * K_DIM];
                const __half2* xr = (const __half2*)&g_X16[(size_t)grow * K_DIM];
                float s = 0.f;
                for (int kk = 0; kk < K_DIM / 2; ++kk) {
                    float2 a = __half22float2(xr[kk]);
                    float2 b = __half22float2(wr[kk]);
                    s += a.x * b.x + a.y * b.y;
                }
                s += bd[soma];
                s = s >= 0.f ? s : 0.1f * s;
                o += s * Ws[(size_t)neuron * NSOMA + soma];
            }
            o += bs[neuron];
            o = o >= 0.f ? o : 0.1f * o;
            out[(size_t)grow * NNEUR + neuron] = o;
        }
    }
#endif
}

// ---------- host ----------
typedef CUresult (*EncodeFn)(CUtensorMap*, CUtensorMapDataType, cuuint32_t, void*,
                             const cuuint64_t*, const cuuint64_t*, const cuuint32_t*,
                             const cuuint32_t*, CUtensorMapInterleave, CUtensorMapSwizzle,
                             CUtensorMapL2promotion, CUtensorMapFloatOOBfill);

static void make_map(EncodeFn enc, CUtensorMap* map, void* ptr,
                     uint64_t rows, uint32_t box_rows)
{
    cuuint64_t dims[2]    = {K_DIM, rows};
    cuuint64_t strides[1] = {K_DIM * 2};
    cuuint32_t box[2]     = {KC, box_rows};
    cuuint32_t es[2]      = {1, 1};
    enc(map, CU_TENSOR_MAP_DATA_TYPE_FLOAT16, 2, ptr, dims, strides, box, es,
        CU_TENSOR_MAP_INTERLEAVE_NONE, CU_TENSOR_MAP_SWIZZLE_128B,
        CU_TENSOR_MAP_L2_PROMOTION_L2_128B, CU_TENSOR_MAP_FLOAT_OOB_FILL_NONE);
}

extern "C" void kernel_launch(void* const* d_in, const int* in_sizes, int n_in,
                              void* d_out, int out_size)
{
    const float* x    = (const float*)d_in[0];
    const float* Wd   = (const float*)d_in[1];
    const float* bd   = (const float*)d_in[2];
    const float* Ws   = (const float*)d_in[3];
    const float* bs   = (const float*)d_in[4];
    const float* dmask= (const float*)d_in[5];
    float* out = (float*)d_out;

    void* px; void* pw;
    cudaGetSymbolAddress(&px, g_X16);
    cudaGetSymbolAddress(&pw, g_W16);

    cudaDriverEntryPointQueryResult qr;
    void* fn = nullptr;
    cudaGetDriverEntryPointByVersion("cuTensorMapEncodeTiled", &fn, 12000,
                                     cudaEnableDefault, &qr);
    EncodeFn enc = (EncodeFn)fn;

    CUtensorMap tmA, tmB;
    make_map(enc, &tmA, px, B_DIM, 128);   // A box: 64 x 128
    make_map(enc, &tmB, pw, NSOMA, 128);   // B box: 64 x 128

    cudaFuncSetAttribute(fused_gemm, cudaFuncAttributeMaxDynamicSharedMemorySize, SMEM_BYTES);

    int n8x = B_DIM * K_DIM / 8;     // 524288
    int n8w = NSOMA * K_DIM / 8;     // 2097152
    int total = n8x + n8w;
    cvt_all_kernel<<<(total + 255) / 256, 256>>>((const float4*)x, (const float4*)Wd,
                                                 (const float4*)dmask,
                                                 (uint4*)px, (uint4*)pw, n8x, n8w);
    fused_gemm<<<148, 288, SMEM_BYTES>>>(tmA, tmB, bd, Ws, bs, out);
}